// round 14
// baseline (speedup 1.0000x reference)
#include <cuda_runtime.h>
#include <cuda_bf16.h>
#include <math.h>
#include <stdint.h>

// Problem constants
#define Bm 256      // batch
#define Tt 128      // timesteps
#define Ff 1280     // features
#define Hh 256      // hidden
#define G4 1024     // 4*H

// ---------------------------------------------------------------------------
// Scratch (allocation-free: __device__ globals)
// ---------------------------------------------------------------------------
__device__ float g_xz[(size_t)Bm * Tt * G4];          // x@W + bias, [B][T][4H]
__device__ float g_c[Bm * Hh];                         // cell state (fp32)
__device__ __nv_bfloat16 g_h_hi[2][Bm * Hh];           // h hi split, ping-pong
__device__ __nv_bfloat16 g_h_lo[2][Bm * Hh];           // h lo split, ping-pong
__device__ __nv_bfloat16 g_Wt_hi[(size_t)G4 * Ff];     // W^T hi split, [1024][1280]
__device__ __nv_bfloat16 g_Wt_lo[(size_t)G4 * Ff];     // W^T lo split
__device__ __nv_bfloat16 g_Rt_hi[(size_t)G4 * Hh];     // R^T hi split, [1024][256]
__device__ __nv_bfloat16 g_Rt_lo[(size_t)G4 * Hh];     // R^T lo split
__device__ __nv_bfloat16 g_x_hi[(size_t)Bm * Tt * Ff]; // x hi split
__device__ __nv_bfloat16 g_x_lo[(size_t)Bm * Tt * Ff]; // x lo split
__device__ unsigned int g_bar;                         // global barrier counter

// ---------------------------------------------------------------------------
// Init: zero h0 (bf16 splits), c0, barrier counter
// ---------------------------------------------------------------------------
__global__ void init_state_kernel() {
    int idx = blockIdx.x * blockDim.x + threadIdx.x;
    if (idx == 0) g_bar = 0u;
    if (idx < Bm * Hh) {
        g_c[idx] = 0.0f;
        g_h_hi[0][idx] = __float2bfloat16_rn(0.0f);
        g_h_lo[0][idx] = __float2bfloat16_rn(0.0f);
    }
}

__device__ __forceinline__ uint32_t pack_bf16(__nv_bfloat16 a, __nv_bfloat16 b) {
    uint32_t lo16 = (uint32_t)__bfloat16_as_ushort(a);
    uint32_t hi16 = (uint32_t)__bfloat16_as_ushort(b);
    return lo16 | (hi16 << 16);
}

// ---------------------------------------------------------------------------
// x -> bf16 hi/lo split (one shot, memory bound)
// ---------------------------------------------------------------------------
__global__ __launch_bounds__(256) void convert_x_kernel(const float* __restrict__ x) {
    size_t i = (size_t)blockIdx.x * blockDim.x + threadIdx.x;   // float4 index
    const size_t n4 = (size_t)Bm * Tt * Ff / 4;
    if (i >= n4) return;
    float4 v = ((const float4*)x)[i];
    __nv_bfloat16 hx = __float2bfloat16_rn(v.x);
    __nv_bfloat16 hy = __float2bfloat16_rn(v.y);
    __nv_bfloat16 hz = __float2bfloat16_rn(v.z);
    __nv_bfloat16 hw = __float2bfloat16_rn(v.w);
    __nv_bfloat16 lx = __float2bfloat16_rn(v.x - __bfloat162float(hx));
    __nv_bfloat16 ly = __float2bfloat16_rn(v.y - __bfloat162float(hy));
    __nv_bfloat16 lz = __float2bfloat16_rn(v.z - __bfloat162float(hz));
    __nv_bfloat16 lw = __float2bfloat16_rn(v.w - __bfloat162float(hw));
    ((uint2*)g_x_hi)[i] = make_uint2(pack_bf16(hx, hy), pack_bf16(hz, hw));
    ((uint2*)g_x_lo)[i] = make_uint2(pack_bf16(lx, ly), pack_bf16(lz, lw));
}

// ---------------------------------------------------------------------------
// W transpose + bf16 hi/lo split: Wt[n][k] = split(W[k][n]),  [1024][1280]
// ---------------------------------------------------------------------------
__global__ __launch_bounds__(256) void convert_w_kernel(const float* __restrict__ W) {
    __shared__ float tile[32][33];
    const int nb = blockIdx.x * 32;
    const int kb = blockIdx.y * 32;
    const int tx = threadIdx.x;
    const int ty = threadIdx.y;

#pragma unroll
    for (int j = 0; j < 32; j += 8)
        tile[ty + j][tx] = W[(size_t)(kb + ty + j) * G4 + nb + tx];
    __syncthreads();

#pragma unroll
    for (int j = 0; j < 32; j += 8) {
        float v = tile[tx][ty + j];
        __nv_bfloat16 hi = __float2bfloat16_rn(v);
        __nv_bfloat16 lo = __float2bfloat16_rn(v - __bfloat162float(hi));
        size_t off = (size_t)(nb + ty + j) * Ff + kb + tx;
        g_Wt_hi[off] = hi;
        g_Wt_lo[off] = lo;
    }
}

// ---------------------------------------------------------------------------
// R transpose + bf16 hi/lo split: Rt[n][k] = split(R[k][n]),  [1024][256]
// ---------------------------------------------------------------------------
__global__ __launch_bounds__(256) void convert_r_kernel(const float* __restrict__ R) {
    __shared__ float tile[32][33];
    const int nb = blockIdx.x * 32;   // over 1024
    const int kb = blockIdx.y * 32;   // over 256
    const int tx = threadIdx.x;
    const int ty = threadIdx.y;

#pragma unroll
    for (int j = 0; j < 32; j += 8)
        tile[ty + j][tx] = R[(size_t)(kb + ty + j) * G4 + nb + tx];
    __syncthreads();

#pragma unroll
    for (int j = 0; j < 32; j += 8) {
        float v = tile[tx][ty + j];
        __nv_bfloat16 hi = __float2bfloat16_rn(v);
        __nv_bfloat16 lo = __float2bfloat16_rn(v - __bfloat162float(hi));
        size_t off = (size_t)(nb + ty + j) * Hh + kb + tx;
        g_Rt_hi[off] = hi;
        g_Rt_lo[off] = lo;
    }
}

// ---------------------------------------------------------------------------
// Shared PTX helpers
// ---------------------------------------------------------------------------
__device__ __forceinline__ void cpasync16(uint32_t saddr, const void* gaddr) {
    asm volatile("cp.async.cg.shared.global [%0], [%1], 16;\n"
                 :: "r"(saddr), "l"(gaddr));
}
__device__ __forceinline__ void cp_commit() {
    asm volatile("cp.async.commit_group;\n");
}
template <int N>
__device__ __forceinline__ void cp_wait() {
    asm volatile("cp.async.wait_group %0;\n" :: "n"(N));
}
__device__ __forceinline__ void ldsm_x4(uint32_t& r0, uint32_t& r1,
                                        uint32_t& r2, uint32_t& r3, uint32_t a) {
    asm volatile("ldmatrix.sync.aligned.m8n8.x4.shared.b16 {%0,%1,%2,%3}, [%4];\n"
                 : "=r"(r0), "=r"(r1), "=r"(r2), "=r"(r3) : "r"(a));
}
__device__ __forceinline__ void mma16816(
    float& d0, float& d1, float& d2, float& d3,
    uint32_t a0, uint32_t a1, uint32_t a2, uint32_t a3,
    uint32_t b0, uint32_t b1)
{
    asm volatile(
        "mma.sync.aligned.m16n8k16.row.col.f32.bf16.bf16.f32 "
        "{%0,%1,%2,%3}, {%4,%5,%6,%7}, {%8,%9}, {%0,%1,%2,%3};\n"
        : "+f"(d0), "+f"(d1), "+f"(d2), "+f"(d3)
        : "r"(a0), "r"(a1), "r"(a2), "r"(a3), "r"(b0), "r"(b1));
}

// ---------------------------------------------------------------------------
// Phase 1 GEMM: xz = x @ W + bias via split-bf16 mma.sync (3 products).
// 128x128 block tile, BK=16 halves, 3-stage cp.async pipeline, ldmatrix frags.
// NOTE: target is sm_100 (no 'a') — tcgen05 unavailable; legacy mma.sync is
// the tensor path. This round: __launch_bounds__(256, 2) -> 2 CTAs/SM
// (96KB smem, regs capped 128) to hide LDS/MMA latency + barrier waits.
// ---------------------------------------------------------------------------
#define MAT_B 4096
#define A_HI_OFF 0
#define A_LO_OFF (1 * MAT_B)
#define B_HI_OFF (2 * MAT_B)
#define B_LO_OFF (3 * MAT_B)
#define STAGE_B (4 * MAT_B)
#define NSTAGE 3
#define NKT (Ff / 16)

__device__ __forceinline__ uint32_t sw_off(int row, int chunk) {
    return (uint32_t)(row * 32 + ((chunk ^ ((row >> 2) & 1)) << 4));
}

__global__ __launch_bounds__(256, 2) void gemm_xz_kernel(const float* __restrict__ bias)
{
    __shared__ __align__(16) unsigned char smem[NSTAGE * STAGE_B];   // 48KB

    const int tid  = threadIdx.x;
    const int lane = tid & 31;
    const int wid  = tid >> 5;
    const int wm   = wid >> 2;
    const int wn   = wid & 3;
    const int m0   = blockIdx.y * 128;
    const int n0   = blockIdx.x * 128;
    const int g    = lane >> 2;
    const int kq   = lane & 3;

    const uint32_t smem_u32 = (uint32_t)__cvta_generic_to_shared(smem);

    const int l_row = tid >> 1;
    const int l_ch  = tid & 1;
    const uint32_t l_soff = sw_off(l_row, l_ch);

    float acc[4][4][4];
#pragma unroll
    for (int i = 0; i < 4; i++)
#pragma unroll
        for (int j = 0; j < 4; j++)
#pragma unroll
            for (int r = 0; r < 4; r++) acc[i][j][r] = 0.0f;

    auto load_stage = [&](int kt, int s) {
        const int k0 = kt * 16;
        const uint32_t sb = smem_u32 + s * STAGE_B;
        size_t ga = (size_t)(m0 + l_row) * Ff + k0 + l_ch * 8;
        size_t gb = (size_t)(n0 + l_row) * Ff + k0 + l_ch * 8;
        cpasync16(sb + A_HI_OFF + l_soff, g_x_hi + ga);
        cpasync16(sb + A_LO_OFF + l_soff, g_x_lo + ga);
        cpasync16(sb + B_HI_OFF + l_soff, g_Wt_hi + gb);
        cpasync16(sb + B_LO_OFF + l_soff, g_Wt_lo + gb);
    };

    const int a_row = lane & 15;
    const int a_kc  = lane >> 4;
    const int b_row = lane & 7;
    const int b_kc  = (lane >> 3) & 1;
    const int b_tl  = (lane >> 4) & 1;

    load_stage(0, 0); cp_commit();
    load_stage(1, 1); cp_commit();

    int s_cur = 0, s_nxt = 2;
    for (int kt = 0; kt < NKT; kt++) {
        if (kt == NKT - 1) cp_wait<0>(); else cp_wait<1>();
        __syncthreads();

        if (kt + 2 < NKT) {
            load_stage(kt + 2, s_nxt);
            cp_commit();
        }

        const uint32_t sb = smem_u32 + s_cur * STAGE_B;

        uint32_t ahi[4][4], alo[4][4], bhi[4][2], blo[4][2];
#pragma unroll
        for (int mt = 0; mt < 4; mt++) {
            int row = wm * 64 + mt * 16 + a_row;
            uint32_t off = sw_off(row, a_kc);
            ldsm_x4(ahi[mt][0], ahi[mt][1], ahi[mt][2], ahi[mt][3],
                    sb + A_HI_OFF + off);
            ldsm_x4(alo[mt][0], alo[mt][1], alo[mt][2], alo[mt][3],
                    sb + A_LO_OFF + off);
        }
#pragma unroll
        for (int bt = 0; bt < 2; bt++) {
            int row = wn * 32 + (2 * bt + b_tl) * 8 + b_row;
            uint32_t off = sw_off(row, b_kc);
            ldsm_x4(bhi[2 * bt][0], bhi[2 * bt][1],
                    bhi[2 * bt + 1][0], bhi[2 * bt + 1][1],
                    sb + B_HI_OFF + off);
            ldsm_x4(blo[2 * bt][0], blo[2 * bt][1],
                    blo[2 * bt + 1][0], blo[2 * bt + 1][1],
                    sb + B_LO_OFF + off);
        }
#pragma unroll
        for (int mt = 0; mt < 4; mt++)
#pragma unroll
            for (int nt = 0; nt < 4; nt++) {
                float* d = acc[mt][nt];
                mma16816(d[0], d[1], d[2], d[3],
                         ahi[mt][0], ahi[mt][1], ahi[mt][2], ahi[mt][3],
                         bhi[nt][0], bhi[nt][1]);
                mma16816(d[0], d[1], d[2], d[3],
                         ahi[mt][0], ahi[mt][1], ahi[mt][2], ahi[mt][3],
                         blo[nt][0], blo[nt][1]);
                mma16816(d[0], d[1], d[2], d[3],
                         alo[mt][0], alo[mt][1], alo[mt][2], alo[mt][3],
                         bhi[nt][0], bhi[nt][1]);
            }

        s_cur = (s_cur == 2) ? 0 : s_cur + 1;
        s_nxt = (s_nxt == 2) ? 0 : s_nxt + 1;
    }

#pragma unroll
    for (int mt = 0; mt < 4; mt++) {
#pragma unroll
        for (int nt = 0; nt < 4; nt++) {
            int row = m0 + wm * 64 + mt * 16 + g;
            int col = n0 + wn * 32 + nt * 8 + kq * 2;
            float b0 = bias[col], b1 = bias[col + 1];
            float2 v0 = make_float2(acc[mt][nt][0] + b0, acc[mt][nt][1] + b1);
            float2 v1 = make_float2(acc[mt][nt][2] + b0, acc[mt][nt][3] + b1);
            *(float2*)(g_xz + (size_t)row * G4 + col)       = v0;
            *(float2*)(g_xz + (size_t)(row + 8) * G4 + col) = v1;
        }
    }
}

// ---------------------------------------------------------------------------
// Phase 2: ONE persistent kernel, all 128 timesteps (unchanged — passing R11).
// ---------------------------------------------------------------------------
#define P2_AB 16384                 // bytes per A split (32 x 512)
#define P2_BB 32768                 // bytes per B split (64 x 512)
#define P2_AHI 0
#define P2_ALO (P2_AB)
#define P2_BHI (2 * P2_AB)
#define P2_BLO (2 * P2_AB + P2_BB)
#define P2_ZS  (2 * P2_AB + 2 * P2_BB)              // Zs: 32x64 fp32 = 8KB
#define P2_SMEM (2 * P2_AB + 2 * P2_BB + 8192)      // 106496 B

__device__ __forceinline__ uint32_t swz(int row, int unit) {
    return (uint32_t)(row * 512 + ((unit ^ (row & 7)) << 4));
}

__device__ __forceinline__ float sigf(float v) {
    return 1.0f / (1.0f + expf(-v));
}

extern __shared__ __align__(16) unsigned char p2_smem[];

__global__ __launch_bounds__(256) void lstm_persistent_kernel(
    float* __restrict__ out)        // [256, 256]
{
    const int tid  = threadIdx.x;
    const int lane = tid & 31;
    const int wid  = tid >> 5;
    const int wm   = wid >> 2;          // 0..1 -> m offset wm*16
    const int wn   = wid & 3;           // 0..3 -> 16 z-cols each
    const int hc0  = blockIdx.x * 16;   // h-col tile base
    const int b0   = blockIdx.y * 32;   // batch tile base
    const int g    = lane >> 2;
    const int kq   = lane & 3;

    const uint32_t sm = (uint32_t)__cvta_generic_to_shared(p2_smem);
    float* Zs = (float*)(p2_smem + P2_ZS);

    // fragment lane coords
    const int a_row = lane & 15;
    const int a_kc  = lane >> 4;
    const int b_row = lane & 7;
    const int b_kc  = (lane >> 3) & 1;
    const int b_tl  = (lane >> 4) & 1;

    // ---- load B (R slice) once: 64 z-cols x 256 k, hi+lo ----
#pragma unroll
    for (int i = 0; i < 8; i++) {
        int e   = tid + i * 256;       // 0..2047
        int row = e >> 5;              // local z-col 0..63
        int un  = e & 31;              // 16B unit
        int gate = row >> 4;
        int hl   = row & 15;
        size_t gb = (size_t)(gate * 256 + hc0 + hl) * Hh + un * 8;
        uint32_t so = swz(row, un);
        cpasync16(sm + P2_BHI + so, g_Rt_hi + gb);
        cpasync16(sm + P2_BLO + so, g_Rt_lo + gb);
    }

    // ---- load A (h) ----
    auto load_A = [&](const __nv_bfloat16* hi, const __nv_bfloat16* lo) {
#pragma unroll
        for (int i = 0; i < 4; i++) {
            int e   = tid + i * 256;   // 0..1023
            int row = e >> 5;          // 0..31
            int un  = e & 31;
            size_t ga = (size_t)(b0 + row) * Hh + un * 8;
            uint32_t so = swz(row, un);
            cpasync16(sm + P2_AHI + so, hi + ga);
            cpasync16(sm + P2_ALO + so, lo + ga);
        }
    };
    load_A(g_h_hi[0], g_h_lo[0]);
    cp_commit();
    cp_wait<0>();
    __syncthreads();

    const unsigned int nCTA = gridDim.x * gridDim.y;

    for (int t = 0; t < Tt; t++) {
        // ---- GEMM: z = h @ Rt (3-product split bf16), K=256 ----
        float acc[2][4];
#pragma unroll
        for (int nt = 0; nt < 2; nt++)
#pragma unroll
            for (int r = 0; r < 4; r++) acc[nt][r] = 0.0f;

#pragma unroll
        for (int kc = 0; kc < 16; kc++) {
            uint32_t ahi[4], alo[4], bhi[2][2], blo[2][2];
            {
                uint32_t off = swz(wm * 16 + a_row, kc * 2 + a_kc);
                ldsm_x4(ahi[0], ahi[1], ahi[2], ahi[3], sm + P2_AHI + off);
                ldsm_x4(alo[0], alo[1], alo[2], alo[3], sm + P2_ALO + off);
            }
            {
                int row = wn * 16 + b_tl * 8 + b_row;
                uint32_t off = swz(row, kc * 2 + b_kc);
                ldsm_x4(bhi[0][0], bhi[0][1], bhi[1][0], bhi[1][1],
                        sm + P2_BHI + off);
                ldsm_x4(blo[0][0], blo[0][1], blo[1][0], blo[1][1],
                        sm + P2_BLO + off);
            }
#pragma unroll
            for (int nt = 0; nt < 2; nt++) {
                float* d = acc[nt];
                mma16816(d[0], d[1], d[2], d[3],
                         ahi[0], ahi[1], ahi[2], ahi[3],
                         bhi[nt][0], bhi[nt][1]);
                mma16816(d[0], d[1], d[2], d[3],
                         ahi[0], ahi[1], ahi[2], ahi[3],
                         blo[nt][0], blo[nt][1]);
                mma16816(d[0], d[1], d[2], d[3],
                         alo[0], alo[1], alo[2], alo[3],
                         bhi[nt][0], bhi[nt][1]);
            }
        }

        // ---- stage z to smem ----
        __syncthreads();
#pragma unroll
        for (int nt = 0; nt < 2; nt++) {
            int r   = wm * 16 + g;
            int col = wn * 16 + nt * 8 + kq * 2;
            *(float2*)&Zs[r * 64 + col]       = make_float2(acc[nt][0], acc[nt][1]);
            *(float2*)&Zs[(r + 8) * 64 + col] = make_float2(acc[nt][2], acc[nt][3]);
        }
        __syncthreads();

        // ---- fused gate/cell update: 32 rows x 16 h-cols = 512 elems ----
        __nv_bfloat16* __restrict__ hn_hi = g_h_hi[(t + 1) & 1];
        __nv_bfloat16* __restrict__ hn_lo = g_h_lo[(t + 1) & 1];
#pragma unroll
        for (int i = 0; i < 2; i++) {
            int e  = tid + i * 256;    // 0..511
            int r  = e >> 4;           // 0..31
            int hl = e & 15;           // 0..15

            size_t xzrow = ((size_t)(b0 + r) * Tt + t) * G4;
            float zi = Zs[r * 64 + hl]      + g_xz[xzrow + 0 * 256 + hc0 + hl];
            float zf = Zs[r * 64 + 16 + hl] + g_xz[xzrow + 1 * 256 + hc0 + hl];
            float zg = Zs[r * 64 + 32 + hl] + g_xz[xzrow + 2 * 256 + hc0 + hl];
            float zo = Zs[r * 64 + 48 + hl] + g_xz[xzrow + 3 * 256 + hc0 + hl];

            int idx = (b0 + r) * Hh + hc0 + hl;
            float cn = sigf(zf) * g_c[idx] + sigf(zi) * tanhf(zg);
            g_c[idx] = cn;
            float hn = sigf(zo) * tanhf(cn);

            __nv_bfloat16 hhi = __float2bfloat16_rn(hn);
            __nv_bfloat16 hlo = __float2bfloat16_rn(hn - __bfloat162float(hhi));
            hn_hi[idx] = hhi;
            hn_lo[idx] = hlo;
            if (t == Tt - 1) out[idx] = hn;
        }

        if (t == Tt - 1) break;   // no barrier needed after last step

        // ---- device-wide barrier ----
        __syncthreads();
        if (tid == 0) {
            __threadfence();
            atomicAdd(&g_bar, 1u);
            unsigned int target = (unsigned int)(t + 1) * nCTA;
            while (*(volatile unsigned int*)&g_bar < target) __nanosleep(64);
        }
        __syncthreads();

        // ---- load next h (written by all CTAs, fenced by barrier) ----
        load_A(g_h_hi[(t + 1) & 1], g_h_lo[(t + 1) & 1]);
        cp_commit();
        cp_wait<0>();
        __syncthreads();
    }
}

// ---------------------------------------------------------------------------
// Launch (stateless, capture-safe)
// ---------------------------------------------------------------------------
extern "C" void kernel_launch(void* const* d_in, const int* in_sizes, int n_in,
                              void* d_out, int out_size)
{
    const float* x    = (const float*)d_in[0];   // [256, 128, 1280]
    const float* W    = (const float*)d_in[1];   // [1280, 1024]
    const float* R    = (const float*)d_in[2];   // [256, 1024]
    const float* bias = (const float*)d_in[3];   // [1024]
    float* out = (float*)d_out;                  // [256, 256]

    (void)in_sizes; (void)n_in; (void)out_size;

    init_state_kernel<<<(Bm * Hh + 511) / 512, 512>>>();

    // One-shot conversions
    convert_w_kernel<<<dim3(G4 / 32, Ff / 32), dim3(32, 8)>>>(W);
    convert_r_kernel<<<dim3(G4 / 32, Hh / 32), dim3(32, 8)>>>(R);
    convert_x_kernel<<<(unsigned)(((size_t)Bm * Tt * Ff / 4 + 255) / 256), 256>>>(x);

    // Phase 1: xz = x @ W + bias (mma.sync tensor cores, 3-stage cp.async,
    // 2 CTAs/SM)
    gemm_xz_kernel<<<dim3(G4 / 128, (Bm * Tt) / 128), 256>>>(bias);

    // Phase 2: one persistent kernel, 128 timesteps, global barrier per step.
    cudaFuncSetAttribute(lstm_persistent_kernel,
                         cudaFuncAttributeMaxDynamicSharedMemorySize, P2_SMEM);
    lstm_persistent_kernel<<<dim3(Hh / 16, Bm / 32), 256, P2_SMEM>>>(out);
}

// round 15
// speedup vs baseline: 1.0280x; 1.0280x over previous
#include <cuda_runtime.h>
#include <cuda_bf16.h>
#include <math.h>
#include <stdint.h>

// Problem constants
#define Bm 256      // batch
#define Tt 128      // timesteps
#define Ff 1280     // features
#define Hh 256      // hidden
#define G4 1024     // 4*H

// ---------------------------------------------------------------------------
// Scratch (allocation-free: __device__ globals)
// ---------------------------------------------------------------------------
__device__ float g_xz[(size_t)Bm * Tt * G4];          // x@W + bias, [B][T][4H]
__device__ float g_c[Bm * Hh];                         // cell state (fp32)
__device__ __nv_bfloat16 g_h_hi[2][Bm * Hh];           // h hi split, ping-pong
__device__ __nv_bfloat16 g_h_lo[2][Bm * Hh];           // h lo split, ping-pong
__device__ __nv_bfloat16 g_Wt_hi[(size_t)G4 * Ff];     // W^T hi split, [1024][1280]
__device__ __nv_bfloat16 g_Wt_lo[(size_t)G4 * Ff];     // W^T lo split
__device__ __nv_bfloat16 g_Rt_hi[(size_t)G4 * Hh];     // R^T hi split, [1024][256]
__device__ __nv_bfloat16 g_Rt_lo[(size_t)G4 * Hh];     // R^T lo split
__device__ __nv_bfloat16 g_x_hi[(size_t)Bm * Tt * Ff]; // x hi split
__device__ __nv_bfloat16 g_x_lo[(size_t)Bm * Tt * Ff]; // x lo split
__device__ unsigned int g_bars[8 * 32];                // per-batch-group barrier
                                                       // counters (128B padded)

// ---------------------------------------------------------------------------
// Init: zero h0 (bf16 splits), c0, barrier counters
// ---------------------------------------------------------------------------
__global__ void init_state_kernel() {
    int idx = blockIdx.x * blockDim.x + threadIdx.x;
    if (idx < 8 * 32) g_bars[idx] = 0u;
    if (idx < Bm * Hh) {
        g_c[idx] = 0.0f;
        g_h_hi[0][idx] = __float2bfloat16_rn(0.0f);
        g_h_lo[0][idx] = __float2bfloat16_rn(0.0f);
    }
}

__device__ __forceinline__ uint32_t pack_bf16(__nv_bfloat16 a, __nv_bfloat16 b) {
    uint32_t lo16 = (uint32_t)__bfloat16_as_ushort(a);
    uint32_t hi16 = (uint32_t)__bfloat16_as_ushort(b);
    return lo16 | (hi16 << 16);
}

// ---------------------------------------------------------------------------
// x -> bf16 hi/lo split (one shot, memory bound)
// ---------------------------------------------------------------------------
__global__ __launch_bounds__(256) void convert_x_kernel(const float* __restrict__ x) {
    size_t i = (size_t)blockIdx.x * blockDim.x + threadIdx.x;   // float4 index
    const size_t n4 = (size_t)Bm * Tt * Ff / 4;
    if (i >= n4) return;
    float4 v = ((const float4*)x)[i];
    __nv_bfloat16 hx = __float2bfloat16_rn(v.x);
    __nv_bfloat16 hy = __float2bfloat16_rn(v.y);
    __nv_bfloat16 hz = __float2bfloat16_rn(v.z);
    __nv_bfloat16 hw = __float2bfloat16_rn(v.w);
    __nv_bfloat16 lx = __float2bfloat16_rn(v.x - __bfloat162float(hx));
    __nv_bfloat16 ly = __float2bfloat16_rn(v.y - __bfloat162float(hy));
    __nv_bfloat16 lz = __float2bfloat16_rn(v.z - __bfloat162float(hz));
    __nv_bfloat16 lw = __float2bfloat16_rn(v.w - __bfloat162float(hw));
    ((uint2*)g_x_hi)[i] = make_uint2(pack_bf16(hx, hy), pack_bf16(hz, hw));
    ((uint2*)g_x_lo)[i] = make_uint2(pack_bf16(lx, ly), pack_bf16(lz, lw));
}

// ---------------------------------------------------------------------------
// W transpose + bf16 hi/lo split: Wt[n][k] = split(W[k][n]),  [1024][1280]
// ---------------------------------------------------------------------------
__global__ __launch_bounds__(256) void convert_w_kernel(const float* __restrict__ W) {
    __shared__ float tile[32][33];
    const int nb = blockIdx.x * 32;
    const int kb = blockIdx.y * 32;
    const int tx = threadIdx.x;
    const int ty = threadIdx.y;

#pragma unroll
    for (int j = 0; j < 32; j += 8)
        tile[ty + j][tx] = W[(size_t)(kb + ty + j) * G4 + nb + tx];
    __syncthreads();

#pragma unroll
    for (int j = 0; j < 32; j += 8) {
        float v = tile[tx][ty + j];
        __nv_bfloat16 hi = __float2bfloat16_rn(v);
        __nv_bfloat16 lo = __float2bfloat16_rn(v - __bfloat162float(hi));
        size_t off = (size_t)(nb + ty + j) * Ff + kb + tx;
        g_Wt_hi[off] = hi;
        g_Wt_lo[off] = lo;
    }
}

// ---------------------------------------------------------------------------
// R transpose + bf16 hi/lo split: Rt[n][k] = split(R[k][n]),  [1024][256]
// ---------------------------------------------------------------------------
__global__ __launch_bounds__(256) void convert_r_kernel(const float* __restrict__ R) {
    __shared__ float tile[32][33];
    const int nb = blockIdx.x * 32;   // over 1024
    const int kb = blockIdx.y * 32;   // over 256
    const int tx = threadIdx.x;
    const int ty = threadIdx.y;

#pragma unroll
    for (int j = 0; j < 32; j += 8)
        tile[ty + j][tx] = R[(size_t)(kb + ty + j) * G4 + nb + tx];
    __syncthreads();

#pragma unroll
    for (int j = 0; j < 32; j += 8) {
        float v = tile[tx][ty + j];
        __nv_bfloat16 hi = __float2bfloat16_rn(v);
        __nv_bfloat16 lo = __float2bfloat16_rn(v - __bfloat162float(hi));
        size_t off = (size_t)(nb + ty + j) * Hh + kb + tx;
        g_Rt_hi[off] = hi;
        g_Rt_lo[off] = lo;
    }
}

// ---------------------------------------------------------------------------
// Shared PTX helpers
// ---------------------------------------------------------------------------
__device__ __forceinline__ void cpasync16(uint32_t saddr, const void* gaddr) {
    asm volatile("cp.async.cg.shared.global [%0], [%1], 16;\n"
                 :: "r"(saddr), "l"(gaddr));
}
__device__ __forceinline__ void cp_commit() {
    asm volatile("cp.async.commit_group;\n");
}
template <int N>
__device__ __forceinline__ void cp_wait() {
    asm volatile("cp.async.wait_group %0;\n" :: "n"(N));
}
__device__ __forceinline__ void ldsm_x4(uint32_t& r0, uint32_t& r1,
                                        uint32_t& r2, uint32_t& r3, uint32_t a) {
    asm volatile("ldmatrix.sync.aligned.m8n8.x4.shared.b16 {%0,%1,%2,%3}, [%4];\n"
                 : "=r"(r0), "=r"(r1), "=r"(r2), "=r"(r3) : "r"(a));
}
__device__ __forceinline__ void mma16816(
    float& d0, float& d1, float& d2, float& d3,
    uint32_t a0, uint32_t a1, uint32_t a2, uint32_t a3,
    uint32_t b0, uint32_t b1)
{
    asm volatile(
        "mma.sync.aligned.m16n8k16.row.col.f32.bf16.bf16.f32 "
        "{%0,%1,%2,%3}, {%4,%5,%6,%7}, {%8,%9}, {%0,%1,%2,%3};\n"
        : "+f"(d0), "+f"(d1), "+f"(d2), "+f"(d3)
        : "r"(a0), "r"(a1), "r"(a2), "r"(a3), "r"(b0), "r"(b1));
}

// ---------------------------------------------------------------------------
// Phase 1 GEMM: xz = x @ W + bias via split-bf16 mma.sync (3 products).
// 128x128 block tile, BK=16 halves, 3-stage cp.async pipeline, ldmatrix frags.
// (byte-identical to R14 pass)
// ---------------------------------------------------------------------------
#define MAT_B 4096
#define A_HI_OFF 0
#define A_LO_OFF (1 * MAT_B)
#define B_HI_OFF (2 * MAT_B)
#define B_LO_OFF (3 * MAT_B)
#define STAGE_B (4 * MAT_B)
#define NSTAGE 3
#define NKT (Ff / 16)

__device__ __forceinline__ uint32_t sw_off(int row, int chunk) {
    return (uint32_t)(row * 32 + ((chunk ^ ((row >> 2) & 1)) << 4));
}

__global__ __launch_bounds__(256, 2) void gemm_xz_kernel(const float* __restrict__ bias)
{
    __shared__ __align__(16) unsigned char smem[NSTAGE * STAGE_B];   // 48KB

    const int tid  = threadIdx.x;
    const int lane = tid & 31;
    const int wid  = tid >> 5;
    const int wm   = wid >> 2;
    const int wn   = wid & 3;
    const int m0   = blockIdx.y * 128;
    const int n0   = blockIdx.x * 128;
    const int g    = lane >> 2;
    const int kq   = lane & 3;

    const uint32_t smem_u32 = (uint32_t)__cvta_generic_to_shared(smem);

    const int l_row = tid >> 1;
    const int l_ch  = tid & 1;
    const uint32_t l_soff = sw_off(l_row, l_ch);

    float acc[4][4][4];
#pragma unroll
    for (int i = 0; i < 4; i++)
#pragma unroll
        for (int j = 0; j < 4; j++)
#pragma unroll
            for (int r = 0; r < 4; r++) acc[i][j][r] = 0.0f;

    auto load_stage = [&](int kt, int s) {
        const int k0 = kt * 16;
        const uint32_t sb = smem_u32 + s * STAGE_B;
        size_t ga = (size_t)(m0 + l_row) * Ff + k0 + l_ch * 8;
        size_t gb = (size_t)(n0 + l_row) * Ff + k0 + l_ch * 8;
        cpasync16(sb + A_HI_OFF + l_soff, g_x_hi + ga);
        cpasync16(sb + A_LO_OFF + l_soff, g_x_lo + ga);
        cpasync16(sb + B_HI_OFF + l_soff, g_Wt_hi + gb);
        cpasync16(sb + B_LO_OFF + l_soff, g_Wt_lo + gb);
    };

    const int a_row = lane & 15;
    const int a_kc  = lane >> 4;
    const int b_row = lane & 7;
    const int b_kc  = (lane >> 3) & 1;
    const int b_tl  = (lane >> 4) & 1;

    load_stage(0, 0); cp_commit();
    load_stage(1, 1); cp_commit();

    int s_cur = 0, s_nxt = 2;
    for (int kt = 0; kt < NKT; kt++) {
        if (kt == NKT - 1) cp_wait<0>(); else cp_wait<1>();
        __syncthreads();

        if (kt + 2 < NKT) {
            load_stage(kt + 2, s_nxt);
            cp_commit();
        }

        const uint32_t sb = smem_u32 + s_cur * STAGE_B;

        uint32_t ahi[4][4], alo[4][4], bhi[4][2], blo[4][2];
#pragma unroll
        for (int mt = 0; mt < 4; mt++) {
            int row = wm * 64 + mt * 16 + a_row;
            uint32_t off = sw_off(row, a_kc);
            ldsm_x4(ahi[mt][0], ahi[mt][1], ahi[mt][2], ahi[mt][3],
                    sb + A_HI_OFF + off);
            ldsm_x4(alo[mt][0], alo[mt][1], alo[mt][2], alo[mt][3],
                    sb + A_LO_OFF + off);
        }
#pragma unroll
        for (int bt = 0; bt < 2; bt++) {
            int row = wn * 32 + (2 * bt + b_tl) * 8 + b_row;
            uint32_t off = sw_off(row, b_kc);
            ldsm_x4(bhi[2 * bt][0], bhi[2 * bt][1],
                    bhi[2 * bt + 1][0], bhi[2 * bt + 1][1],
                    sb + B_HI_OFF + off);
            ldsm_x4(blo[2 * bt][0], blo[2 * bt][1],
                    blo[2 * bt + 1][0], blo[2 * bt + 1][1],
                    sb + B_LO_OFF + off);
        }
#pragma unroll
        for (int mt = 0; mt < 4; mt++)
#pragma unroll
            for (int nt = 0; nt < 4; nt++) {
                float* d = acc[mt][nt];
                mma16816(d[0], d[1], d[2], d[3],
                         ahi[mt][0], ahi[mt][1], ahi[mt][2], ahi[mt][3],
                         bhi[nt][0], bhi[nt][1]);
                mma16816(d[0], d[1], d[2], d[3],
                         ahi[mt][0], ahi[mt][1], ahi[mt][2], ahi[mt][3],
                         blo[nt][0], blo[nt][1]);
                mma16816(d[0], d[1], d[2], d[3],
                         alo[mt][0], alo[mt][1], alo[mt][2], alo[mt][3],
                         bhi[nt][0], bhi[nt][1]);
            }

        s_cur = (s_cur == 2) ? 0 : s_cur + 1;
        s_nxt = (s_nxt == 2) ? 0 : s_nxt + 1;
    }

#pragma unroll
    for (int mt = 0; mt < 4; mt++) {
#pragma unroll
        for (int nt = 0; nt < 4; nt++) {
            int row = m0 + wm * 64 + mt * 16 + g;
            int col = n0 + wn * 32 + nt * 8 + kq * 2;
            float b0 = bias[col], b1 = bias[col + 1];
            float2 v0 = make_float2(acc[mt][nt][0] + b0, acc[mt][nt][1] + b1);
            float2 v1 = make_float2(acc[mt][nt][2] + b0, acc[mt][nt][3] + b1);
            *(float2*)(g_xz + (size_t)row * G4 + col)       = v0;
            *(float2*)(g_xz + (size_t)(row + 8) * G4 + col) = v1;
        }
    }
}

// ---------------------------------------------------------------------------
// Phase 2: ONE persistent kernel, all 128 timesteps.
// CHANGE vs R14: device-wide barrier -> per-batch-group barrier. h[b0..b0+31]
// is produced only by the 16 CTAs with the same blockIdx.y, so each group of
// 16 syncs on its own padded counter (no chip-wide atomic serialization, no
// cross-group skew coupling). __threadfence before arrival keeps the h writes
// device-visible.
// ---------------------------------------------------------------------------
#define P2_AB 16384                 // bytes per A split (32 x 512)
#define P2_BB 32768                 // bytes per B split (64 x 512)
#define P2_AHI 0
#define P2_ALO (P2_AB)
#define P2_BHI (2 * P2_AB)
#define P2_BLO (2 * P2_AB + P2_BB)
#define P2_ZS  (2 * P2_AB + 2 * P2_BB)              // Zs: 32x64 fp32 = 8KB
#define P2_SMEM (2 * P2_AB + 2 * P2_BB + 8192)      // 106496 B

__device__ __forceinline__ uint32_t swz(int row, int unit) {
    return (uint32_t)(row * 512 + ((unit ^ (row & 7)) << 4));
}

__device__ __forceinline__ float sigf(float v) {
    return 1.0f / (1.0f + expf(-v));
}

extern __shared__ __align__(16) unsigned char p2_smem[];

__global__ __launch_bounds__(256) void lstm_persistent_kernel(
    float* __restrict__ out)        // [256, 256]
{
    const int tid  = threadIdx.x;
    const int lane = tid & 31;
    const int wid  = tid >> 5;
    const int wm   = wid >> 2;          // 0..1 -> m offset wm*16
    const int wn   = wid & 3;           // 0..3 -> 16 z-cols each
    const int hc0  = blockIdx.x * 16;   // h-col tile base
    const int b0   = blockIdx.y * 32;   // batch tile base
    const int g    = lane >> 2;
    const int kq   = lane & 3;

    const uint32_t sm = (uint32_t)__cvta_generic_to_shared(p2_smem);
    float* Zs = (float*)(p2_smem + P2_ZS);

    // fragment lane coords
    const int a_row = lane & 15;
    const int a_kc  = lane >> 4;
    const int b_row = lane & 7;
    const int b_kc  = (lane >> 3) & 1;
    const int b_tl  = (lane >> 4) & 1;

    // per-batch-group barrier state
    unsigned int* bar = &g_bars[blockIdx.y * 32];
    const unsigned int nPeers = gridDim.x;   // 16 CTAs per batch group

    // ---- load B (R slice) once: 64 z-cols x 256 k, hi+lo ----
#pragma unroll
    for (int i = 0; i < 8; i++) {
        int e   = tid + i * 256;       // 0..2047
        int row = e >> 5;              // local z-col 0..63
        int un  = e & 31;              // 16B unit
        int gate = row >> 4;
        int hl   = row & 15;
        size_t gb = (size_t)(gate * 256 + hc0 + hl) * Hh + un * 8;
        uint32_t so = swz(row, un);
        cpasync16(sm + P2_BHI + so, g_Rt_hi + gb);
        cpasync16(sm + P2_BLO + so, g_Rt_lo + gb);
    }

    // ---- load A (h) ----
    auto load_A = [&](const __nv_bfloat16* hi, const __nv_bfloat16* lo) {
#pragma unroll
        for (int i = 0; i < 4; i++) {
            int e   = tid + i * 256;   // 0..1023
            int row = e >> 5;          // 0..31
            int un  = e & 31;
            size_t ga = (size_t)(b0 + row) * Hh + un * 8;
            uint32_t so = swz(row, un);
            cpasync16(sm + P2_AHI + so, hi + ga);
            cpasync16(sm + P2_ALO + so, lo + ga);
        }
    };
    load_A(g_h_hi[0], g_h_lo[0]);
    cp_commit();
    cp_wait<0>();
    __syncthreads();

    for (int t = 0; t < Tt; t++) {
        // ---- GEMM: z = h @ Rt (3-product split bf16), K=256 ----
        float acc[2][4];
#pragma unroll
        for (int nt = 0; nt < 2; nt++)
#pragma unroll
            for (int r = 0; r < 4; r++) acc[nt][r] = 0.0f;

#pragma unroll
        for (int kc = 0; kc < 16; kc++) {
            uint32_t ahi[4], alo[4], bhi[2][2], blo[2][2];
            {
                uint32_t off = swz(wm * 16 + a_row, kc * 2 + a_kc);
                ldsm_x4(ahi[0], ahi[1], ahi[2], ahi[3], sm + P2_AHI + off);
                ldsm_x4(alo[0], alo[1], alo[2], alo[3], sm + P2_ALO + off);
            }
            {
                int row = wn * 16 + b_tl * 8 + b_row;
                uint32_t off = swz(row, kc * 2 + b_kc);
                ldsm_x4(bhi[0][0], bhi[0][1], bhi[1][0], bhi[1][1],
                        sm + P2_BHI + off);
                ldsm_x4(blo[0][0], blo[0][1], blo[1][0], blo[1][1],
                        sm + P2_BLO + off);
            }
#pragma unroll
            for (int nt = 0; nt < 2; nt++) {
                float* d = acc[nt];
                mma16816(d[0], d[1], d[2], d[3],
                         ahi[0], ahi[1], ahi[2], ahi[3],
                         bhi[nt][0], bhi[nt][1]);
                mma16816(d[0], d[1], d[2], d[3],
                         ahi[0], ahi[1], ahi[2], ahi[3],
                         blo[nt][0], blo[nt][1]);
                mma16816(d[0], d[1], d[2], d[3],
                         alo[0], alo[1], alo[2], alo[3],
                         bhi[nt][0], bhi[nt][1]);
            }
        }

        // ---- stage z to smem ----
        __syncthreads();
#pragma unroll
        for (int nt = 0; nt < 2; nt++) {
            int r   = wm * 16 + g;
            int col = wn * 16 + nt * 8 + kq * 2;
            *(float2*)&Zs[r * 64 + col]       = make_float2(acc[nt][0], acc[nt][1]);
            *(float2*)&Zs[(r + 8) * 64 + col] = make_float2(acc[nt][2], acc[nt][3]);
        }
        __syncthreads();

        // ---- fused gate/cell update: 32 rows x 16 h-cols = 512 elems ----
        __nv_bfloat16* __restrict__ hn_hi = g_h_hi[(t + 1) & 1];
        __nv_bfloat16* __restrict__ hn_lo = g_h_lo[(t + 1) & 1];
#pragma unroll
        for (int i = 0; i < 2; i++) {
            int e  = tid + i * 256;    // 0..511
            int r  = e >> 4;           // 0..31
            int hl = e & 15;           // 0..15

            size_t xzrow = ((size_t)(b0 + r) * Tt + t) * G4;
            float zi = Zs[r * 64 + hl]      + g_xz[xzrow + 0 * 256 + hc0 + hl];
            float zf = Zs[r * 64 + 16 + hl] + g_xz[xzrow + 1 * 256 + hc0 + hl];
            float zg = Zs[r * 64 + 32 + hl] + g_xz[xzrow + 2 * 256 + hc0 + hl];
            float zo = Zs[r * 64 + 48 + hl] + g_xz[xzrow + 3 * 256 + hc0 + hl];

            int idx = (b0 + r) * Hh + hc0 + hl;
            float cn = sigf(zf) * g_c[idx] + sigf(zi) * tanhf(zg);
            g_c[idx] = cn;
            float hn = sigf(zo) * tanhf(cn);

            __nv_bfloat16 hhi = __float2bfloat16_rn(hn);
            __nv_bfloat16 hlo = __float2bfloat16_rn(hn - __bfloat162float(hhi));
            hn_hi[idx] = hhi;
            hn_lo[idx] = hlo;
            if (t == Tt - 1) out[idx] = hn;
        }

        if (t == Tt - 1) break;   // no barrier needed after last step

        // ---- per-batch-group barrier (16 CTAs sharing this b0) ----
        __syncthreads();
        if (tid == 0) {
            __threadfence();
            atomicAdd(bar, 1u);
            unsigned int target = (unsigned int)(t + 1) * nPeers;
            while (*(volatile unsigned int*)bar < target) { }
        }
        __syncthreads();

        // ---- load next h (written by this batch group, fenced above) ----
        load_A(g_h_hi[(t + 1) & 1], g_h_lo[(t + 1) & 1]);
        cp_commit();
        cp_wait<0>();
        __syncthreads();
    }
}

// ---------------------------------------------------------------------------
// Launch (stateless, capture-safe)
// ---------------------------------------------------------------------------
extern "C" void kernel_launch(void* const* d_in, const int* in_sizes, int n_in,
                              void* d_out, int out_size)
{
    const float* x    = (const float*)d_in[0];   // [256, 128, 1280]
    const float* W    = (const float*)d_in[1];   // [1280, 1024]
    const float* R    = (const float*)d_in[2];   // [256, 1024]
    const float* bias = (const float*)d_in[3];   // [1024]
    float* out = (float*)d_out;                  // [256, 256]

    (void)in_sizes; (void)n_in; (void)out_size;

    init_state_kernel<<<(Bm * Hh + 511) / 512, 512>>>();

    // One-shot conversions
    convert_w_kernel<<<dim3(G4 / 32, Ff / 32), dim3(32, 8)>>>(W);
    convert_r_kernel<<<dim3(G4 / 32, Hh / 32), dim3(32, 8)>>>(R);
    convert_x_kernel<<<(unsigned)(((size_t)Bm * Tt * Ff / 4 + 255) / 256), 256>>>(x);

    // Phase 1: xz = x @ W + bias (mma.sync tensor cores, 3-stage cp.async)
    gemm_xz_kernel<<<dim3(G4 / 128, (Bm * Tt) / 128), 256>>>(bias);

    // Phase 2: one persistent kernel, 128 timesteps, per-group barriers.
    cudaFuncSetAttribute(lstm_persistent_kernel,
                         cudaFuncAttributeMaxDynamicSharedMemorySize, P2_SMEM);
    lstm_persistent_kernel<<<dim3(Hh / 16, Bm / 32), 256, P2_SMEM>>>(out);
}

// round 17
// speedup vs baseline: 1.0539x; 1.0252x over previous
#include <cuda_runtime.h>
#include <cuda_bf16.h>
#include <math.h>
#include <stdint.h>

// Problem constants
#define Bm 256      // batch
#define Tt 128      // timesteps
#define Ff 1280     // features
#define Hh 256      // hidden
#define G4 1024     // 4*H

// ---------------------------------------------------------------------------
// Scratch (allocation-free: __device__ globals)
// ---------------------------------------------------------------------------
__device__ float g_xz[(size_t)Bm * Tt * G4];          // x@W + bias, [B][T][4H]
__device__ float g_c[Bm * Hh];                         // cell state (fp32)
__device__ __nv_bfloat16 g_h_hi[2][Bm * Hh];           // h hi split, ping-pong
__device__ __nv_bfloat16 g_h_lo[2][Bm * Hh];           // h lo split, ping-pong
__device__ __nv_bfloat16 g_Wt_hi[(size_t)G4 * Ff];     // W^T hi split, [1024][1280]
__device__ __nv_bfloat16 g_Wt_lo[(size_t)G4 * Ff];     // W^T lo split
__device__ __nv_bfloat16 g_Rt_hi[(size_t)G4 * Hh];     // R^T hi split, [1024][256]
__device__ __nv_bfloat16 g_Rt_lo[(size_t)G4 * Hh];     // R^T lo split
__device__ __nv_bfloat16 g_x_hi[(size_t)Bm * Tt * Ff]; // x hi split
__device__ __nv_bfloat16 g_x_lo[(size_t)Bm * Tt * Ff]; // x lo split
__device__ unsigned int g_bars[8 * 32];                // per-batch-group barrier
                                                       // counters (128B padded)

// ---------------------------------------------------------------------------
// Init: zero h0 (bf16 splits), c0, barrier counters
// ---------------------------------------------------------------------------
__global__ void init_state_kernel() {
    int idx = blockIdx.x * blockDim.x + threadIdx.x;
    if (idx < 8 * 32) g_bars[idx] = 0u;
    if (idx < Bm * Hh) {
        g_c[idx] = 0.0f;
        g_h_hi[0][idx] = __float2bfloat16_rn(0.0f);
        g_h_lo[0][idx] = __float2bfloat16_rn(0.0f);
    }
}

__device__ __forceinline__ uint32_t pack_bf16(__nv_bfloat16 a, __nv_bfloat16 b) {
    uint32_t lo16 = (uint32_t)__bfloat16_as_ushort(a);
    uint32_t hi16 = (uint32_t)__bfloat16_as_ushort(b);
    return lo16 | (hi16 << 16);
}

// ---------------------------------------------------------------------------
// x -> bf16 hi/lo split (one shot, memory bound)
// ---------------------------------------------------------------------------
__global__ __launch_bounds__(256) void convert_x_kernel(const float* __restrict__ x) {
    size_t i = (size_t)blockIdx.x * blockDim.x + threadIdx.x;   // float4 index
    const size_t n4 = (size_t)Bm * Tt * Ff / 4;
    if (i >= n4) return;
    float4 v = ((const float4*)x)[i];
    __nv_bfloat16 hx = __float2bfloat16_rn(v.x);
    __nv_bfloat16 hy = __float2bfloat16_rn(v.y);
    __nv_bfloat16 hz = __float2bfloat16_rn(v.z);
    __nv_bfloat16 hw = __float2bfloat16_rn(v.w);
    __nv_bfloat16 lx = __float2bfloat16_rn(v.x - __bfloat162float(hx));
    __nv_bfloat16 ly = __float2bfloat16_rn(v.y - __bfloat162float(hy));
    __nv_bfloat16 lz = __float2bfloat16_rn(v.z - __bfloat162float(hz));
    __nv_bfloat16 lw = __float2bfloat16_rn(v.w - __bfloat162float(hw));
    ((uint2*)g_x_hi)[i] = make_uint2(pack_bf16(hx, hy), pack_bf16(hz, hw));
    ((uint2*)g_x_lo)[i] = make_uint2(pack_bf16(lx, ly), pack_bf16(lz, lw));
}

// ---------------------------------------------------------------------------
// W transpose + bf16 hi/lo split: Wt[n][k] = split(W[k][n]),  [1024][1280]
// ---------------------------------------------------------------------------
__global__ __launch_bounds__(256) void convert_w_kernel(const float* __restrict__ W) {
    __shared__ float tile[32][33];
    const int nb = blockIdx.x * 32;
    const int kb = blockIdx.y * 32;
    const int tx = threadIdx.x;
    const int ty = threadIdx.y;

#pragma unroll
    for (int j = 0; j < 32; j += 8)
        tile[ty + j][tx] = W[(size_t)(kb + ty + j) * G4 + nb + tx];
    __syncthreads();

#pragma unroll
    for (int j = 0; j < 32; j += 8) {
        float v = tile[tx][ty + j];
        __nv_bfloat16 hi = __float2bfloat16_rn(v);
        __nv_bfloat16 lo = __float2bfloat16_rn(v - __bfloat162float(hi));
        size_t off = (size_t)(nb + ty + j) * Ff + kb + tx;
        g_Wt_hi[off] = hi;
        g_Wt_lo[off] = lo;
    }
}

// ---------------------------------------------------------------------------
// R transpose + bf16 hi/lo split: Rt[n][k] = split(R[k][n]),  [1024][256]
// ---------------------------------------------------------------------------
__global__ __launch_bounds__(256) void convert_r_kernel(const float* __restrict__ R) {
    __shared__ float tile[32][33];
    const int nb = blockIdx.x * 32;   // over 1024
    const int kb = blockIdx.y * 32;   // over 256
    const int tx = threadIdx.x;
    const int ty = threadIdx.y;

#pragma unroll
    for (int j = 0; j < 32; j += 8)
        tile[ty + j][tx] = R[(size_t)(kb + ty + j) * G4 + nb + tx];
    __syncthreads();

#pragma unroll
    for (int j = 0; j < 32; j += 8) {
        float v = tile[tx][ty + j];
        __nv_bfloat16 hi = __float2bfloat16_rn(v);
        __nv_bfloat16 lo = __float2bfloat16_rn(v - __bfloat162float(hi));
        size_t off = (size_t)(nb + ty + j) * Hh + kb + tx;
        g_Rt_hi[off] = hi;
        g_Rt_lo[off] = lo;
    }
}

// ---------------------------------------------------------------------------
// Shared PTX helpers
// ---------------------------------------------------------------------------
__device__ __forceinline__ void cpasync16(uint32_t saddr, const void* gaddr) {
    asm volatile("cp.async.cg.shared.global [%0], [%1], 16;\n"
                 :: "r"(saddr), "l"(gaddr));
}
__device__ __forceinline__ void cp_commit() {
    asm volatile("cp.async.commit_group;\n");
}
template <int N>
__device__ __forceinline__ void cp_wait() {
    asm volatile("cp.async.wait_group %0;\n" :: "n"(N));
}
__device__ __forceinline__ void ldsm_x4(uint32_t& r0, uint32_t& r1,
                                        uint32_t& r2, uint32_t& r3, uint32_t a) {
    asm volatile("ldmatrix.sync.aligned.m8n8.x4.shared.b16 {%0,%1,%2,%3}, [%4];\n"
                 : "=r"(r0), "=r"(r1), "=r"(r2), "=r"(r3) : "r"(a));
}
__device__ __forceinline__ void ldsm_x2(uint32_t& r0, uint32_t& r1, uint32_t a) {
    asm volatile("ldmatrix.sync.aligned.m8n8.x2.shared.b16 {%0,%1}, [%2];\n"
                 : "=r"(r0), "=r"(r1) : "r"(a));
}
__device__ __forceinline__ void mma16816(
    float& d0, float& d1, float& d2, float& d3,
    uint32_t a0, uint32_t a1, uint32_t a2, uint32_t a3,
    uint32_t b0, uint32_t b1)
{
    asm volatile(
        "mma.sync.aligned.m16n8k16.row.col.f32.bf16.bf16.f32 "
        "{%0,%1,%2,%3}, {%4,%5,%6,%7}, {%8,%9}, {%0,%1,%2,%3};\n"
        : "+f"(d0), "+f"(d1), "+f"(d2), "+f"(d3)
        : "r"(a0), "r"(a1), "r"(a2), "r"(a3), "r"(b0), "r"(b1));
}

// ---------------------------------------------------------------------------
// Phase 1 GEMM: xz = x @ W + bias via split-bf16 mma.sync (3 products).
// (byte-identical to R15 pass)
// ---------------------------------------------------------------------------
#define MAT_B 4096
#define A_HI_OFF 0
#define A_LO_OFF (1 * MAT_B)
#define B_HI_OFF (2 * MAT_B)
#define B_LO_OFF (3 * MAT_B)
#define STAGE_B (4 * MAT_B)
#define NSTAGE 3
#define NKT (Ff / 16)

__device__ __forceinline__ uint32_t sw_off(int row, int chunk) {
    return (uint32_t)(row * 32 + ((chunk ^ ((row >> 2) & 1)) << 4));
}

__global__ __launch_bounds__(256, 2) void gemm_xz_kernel(const float* __restrict__ bias)
{
    __shared__ __align__(16) unsigned char smem[NSTAGE * STAGE_B];   // 48KB

    const int tid  = threadIdx.x;
    const int lane = tid & 31;
    const int wid  = tid >> 5;
    const int wm   = wid >> 2;
    const int wn   = wid & 3;
    const int m0   = blockIdx.y * 128;
    const int n0   = blockIdx.x * 128;
    const int g    = lane >> 2;
    const int kq   = lane & 3;

    const uint32_t smem_u32 = (uint32_t)__cvta_generic_to_shared(smem);

    const int l_row = tid >> 1;
    const int l_ch  = tid & 1;
    const uint32_t l_soff = sw_off(l_row, l_ch);

    float acc[4][4][4];
#pragma unroll
    for (int i = 0; i < 4; i++)
#pragma unroll
        for (int j = 0; j < 4; j++)
#pragma unroll
            for (int r = 0; r < 4; r++) acc[i][j][r] = 0.0f;

    auto load_stage = [&](int kt, int s) {
        const int k0 = kt * 16;
        const uint32_t sb = smem_u32 + s * STAGE_B;
        size_t ga = (size_t)(m0 + l_row) * Ff + k0 + l_ch * 8;
        size_t gb = (size_t)(n0 + l_row) * Ff + k0 + l_ch * 8;
        cpasync16(sb + A_HI_OFF + l_soff, g_x_hi + ga);
        cpasync16(sb + A_LO_OFF + l_soff, g_x_lo + ga);
        cpasync16(sb + B_HI_OFF + l_soff, g_Wt_hi + gb);
        cpasync16(sb + B_LO_OFF + l_soff, g_Wt_lo + gb);
    };

    const int a_row = lane & 15;
    const int a_kc  = lane >> 4;
    const int b_row = lane & 7;
    const int b_kc  = (lane >> 3) & 1;
    const int b_tl  = (lane >> 4) & 1;

    load_stage(0, 0); cp_commit();
    load_stage(1, 1); cp_commit();

    int s_cur = 0, s_nxt = 2;
    for (int kt = 0; kt < NKT; kt++) {
        if (kt == NKT - 1) cp_wait<0>(); else cp_wait<1>();
        __syncthreads();

        if (kt + 2 < NKT) {
            load_stage(kt + 2, s_nxt);
            cp_commit();
        }

        const uint32_t sb = smem_u32 + s_cur * STAGE_B;

        uint32_t ahi[4][4], alo[4][4], bhi[4][2], blo[4][2];
#pragma unroll
        for (int mt = 0; mt < 4; mt++) {
            int row = wm * 64 + mt * 16 + a_row;
            uint32_t off = sw_off(row, a_kc);
            ldsm_x4(ahi[mt][0], ahi[mt][1], ahi[mt][2], ahi[mt][3],
                    sb + A_HI_OFF + off);
            ldsm_x4(alo[mt][0], alo[mt][1], alo[mt][2], alo[mt][3],
                    sb + A_LO_OFF + off);
        }
#pragma unroll
        for (int bt = 0; bt < 2; bt++) {
            int row = wn * 32 + (2 * bt + b_tl) * 8 + b_row;
            uint32_t off = sw_off(row, b_kc);
            ldsm_x4(bhi[2 * bt][0], bhi[2 * bt][1],
                    bhi[2 * bt + 1][0], bhi[2 * bt + 1][1],
                    sb + B_HI_OFF + off);
            ldsm_x4(blo[2 * bt][0], blo[2 * bt][1],
                    blo[2 * bt + 1][0], blo[2 * bt + 1][1],
                    sb + B_LO_OFF + off);
        }
#pragma unroll
        for (int mt = 0; mt < 4; mt++)
#pragma unroll
            for (int nt = 0; nt < 4; nt++) {
                float* d = acc[mt][nt];
                mma16816(d[0], d[1], d[2], d[3],
                         ahi[mt][0], ahi[mt][1], ahi[mt][2], ahi[mt][3],
                         bhi[nt][0], bhi[nt][1]);
                mma16816(d[0], d[1], d[2], d[3],
                         ahi[mt][0], ahi[mt][1], ahi[mt][2], ahi[mt][3],
                         blo[nt][0], blo[nt][1]);
                mma16816(d[0], d[1], d[2], d[3],
                         alo[mt][0], alo[mt][1], alo[mt][2], alo[mt][3],
                         bhi[nt][0], bhi[nt][1]);
            }

        s_cur = (s_cur == 2) ? 0 : s_cur + 1;
        s_nxt = (s_nxt == 2) ? 0 : s_nxt + 1;
    }

#pragma unroll
    for (int mt = 0; mt < 4; mt++) {
#pragma unroll
        for (int nt = 0; nt < 4; nt++) {
            int row = m0 + wm * 64 + mt * 16 + g;
            int col = n0 + wn * 32 + nt * 8 + kq * 2;
            float b0 = bias[col], b1 = bias[col + 1];
            float2 v0 = make_float2(acc[mt][nt][0] + b0, acc[mt][nt][1] + b1);
            float2 v1 = make_float2(acc[mt][nt][2] + b0, acc[mt][nt][3] + b1);
            *(float2*)(g_xz + (size_t)row * G4 + col)       = v0;
            *(float2*)(g_xz + (size_t)(row + 8) * G4 + col) = v1;
        }
    }
}

// ---------------------------------------------------------------------------
// Phase 2: ONE persistent kernel, all 128 timesteps.
// 512 threads (16 warps -> 4/SMSP, one m16n8 tile per warp), fast-math gates,
// per-batch-group barriers.
// ---------------------------------------------------------------------------
#define P2_AB 16384                 // bytes per A split (32 x 512)
#define P2_BB 32768                 // bytes per B split (64 x 512)
#define P2_AHI 0
#define P2_ALO (P2_AB)
#define P2_BHI (2 * P2_AB)
#define P2_BLO (2 * P2_AB + P2_BB)
#define P2_ZS  (2 * P2_AB + 2 * P2_BB)              // Zs: 32x64 fp32 = 8KB
#define P2_SMEM (2 * P2_AB + 2 * P2_BB + 8192)      // 106496 B
#define P2_THREADS 512

__device__ __forceinline__ uint32_t swz(int row, int unit) {
    return (uint32_t)(row * 512 + ((unit ^ (row & 7)) << 4));
}

__device__ __forceinline__ float sig_fast(float v) {
    return 1.0f / (1.0f + __expf(-v));
}
__device__ __forceinline__ float tanh_fast(float v) {
    // 1 - 2/(e^{2v}+1): saturates to +/-1, no NaN for large |v|
    return 1.0f - 2.0f / (__expf(2.0f * v) + 1.0f);
}

extern __shared__ __align__(16) unsigned char p2_smem[];

__global__ __launch_bounds__(P2_THREADS) void lstm_persistent_kernel(
    float* __restrict__ out)        // [256, 256]
{
    const int tid  = threadIdx.x;
    const int lane = tid & 31;
    const int wid  = tid >> 5;          // 0..15
    const int wm   = wid >> 3;          // 0..1 -> m offset wm*16
    const int wn   = wid & 7;           // 0..7 -> 8 z-cols each
    const int hc0  = blockIdx.x * 16;   // h-col tile base
    const int b0   = blockIdx.y * 32;   // batch tile base
    const int g    = lane >> 2;
    const int kq   = lane & 3;

    const uint32_t sm = (uint32_t)__cvta_generic_to_shared(p2_smem);
    float* Zs = (float*)(p2_smem + P2_ZS);

    // fragment lane coords
    const int a_row = lane & 15;
    const int a_kc  = lane >> 4;
    const int b_row = lane & 7;             // n within this warp's n8 tile
    const int b_kc  = (lane >> 3) & 1;      // k chunk (lanes 0-15 drive x2)

    // per-batch-group barrier state
    unsigned int* bar = &g_bars[blockIdx.y * 32];
    const unsigned int nPeers = gridDim.x;   // 16 CTAs per batch group

    // ---- load B (R slice) once: 64 z-cols x 256 k, hi+lo ----
#pragma unroll
    for (int i = 0; i < 4; i++) {
        int e   = tid + i * P2_THREADS;   // 0..2047
        int row = e >> 5;                 // local z-col 0..63
        int un  = e & 31;                 // 16B unit
        int gate = row >> 4;
        int hl   = row & 15;
        size_t gb = (size_t)(gate * 256 + hc0 + hl) * Hh + un * 8;
        uint32_t so = swz(row, un);
        cpasync16(sm + P2_BHI + so, g_Rt_hi + gb);
        cpasync16(sm + P2_BLO + so, g_Rt_lo + gb);
    }

    // ---- load A (h) ----
    auto load_A = [&](const __nv_bfloat16* hi, const __nv_bfloat16* lo) {
#pragma unroll
        for (int i = 0; i < 2; i++) {
            int e   = tid + i * P2_THREADS;   // 0..1023
            int row = e >> 5;                 // 0..31
            int un  = e & 31;
            size_t ga = (size_t)(b0 + row) * Hh + un * 8;
            uint32_t so = swz(row, un);
            cpasync16(sm + P2_AHI + so, hi + ga);
            cpasync16(sm + P2_ALO + so, lo + ga);
        }
    };
    load_A(g_h_hi[0], g_h_lo[0]);
    cp_commit();
    cp_wait<0>();
    __syncthreads();

    for (int t = 0; t < Tt; t++) {
        // ---- GEMM: z = h @ Rt (3-product split bf16), K=256 ----
        // Each warp: one m16n8 tile, 16 k16-chunks, 3 products = 48 MMA.
        float acc[4];
        acc[0] = acc[1] = acc[2] = acc[3] = 0.0f;

#pragma unroll
        for (int kc = 0; kc < 16; kc++) {
            uint32_t ahi[4], alo[4], bh[2], bl[2];
            {
                uint32_t off = swz(wm * 16 + a_row, kc * 2 + a_kc);
                ldsm_x4(ahi[0], ahi[1], ahi[2], ahi[3], sm + P2_AHI + off);
                ldsm_x4(alo[0], alo[1], alo[2], alo[3], sm + P2_ALO + off);
            }
            {
                int row = wn * 8 + b_row;
                uint32_t off = swz(row, kc * 2 + b_kc);
                ldsm_x2(bh[0], bh[1], sm + P2_BHI + off);
                ldsm_x2(bl[0], bl[1], sm + P2_BLO + off);
            }
            mma16816(acc[0], acc[1], acc[2], acc[3],
                     ahi[0], ahi[1], ahi[2], ahi[3], bh[0], bh[1]);
            mma16816(acc[0], acc[1], acc[2], acc[3],
                     ahi[0], ahi[1], ahi[2], ahi[3], bl[0], bl[1]);
            mma16816(acc[0], acc[1], acc[2], acc[3],
                     alo[0], alo[1], alo[2], alo[3], bh[0], bh[1]);
        }

        // ---- stage z to smem ----
        __syncthreads();
        {
            int r   = wm * 16 + g;
            int col = wn * 8 + kq * 2;
            *(float2*)&Zs[r * 64 + col]       = make_float2(acc[0], acc[1]);
            *(float2*)&Zs[(r + 8) * 64 + col] = make_float2(acc[2], acc[3]);
        }
        __syncthreads();

        // ---- fused gate/cell update: 32 rows x 16 h-cols = 512 elems ----
        __nv_bfloat16* __restrict__ hn_hi = g_h_hi[(t + 1) & 1];
        __nv_bfloat16* __restrict__ hn_lo = g_h_lo[(t + 1) & 1];
        {
            int e  = tid;              // 0..511
            int r  = e >> 4;           // 0..31
            int hl = e & 15;           // 0..15

            size_t xzrow = ((size_t)(b0 + r) * Tt + t) * G4;
            float zi = Zs[r * 64 + hl]      + g_xz[xzrow + 0 * 256 + hc0 + hl];
            float zf = Zs[r * 64 + 16 + hl] + g_xz[xzrow + 1 * 256 + hc0 + hl];
            float zg = Zs[r * 64 + 32 + hl] + g_xz[xzrow + 2 * 256 + hc0 + hl];
            float zo = Zs[r * 64 + 48 + hl] + g_xz[xzrow + 3 * 256 + hc0 + hl];

            int idx = (b0 + r) * Hh + hc0 + hl;
            float cn = sig_fast(zf) * g_c[idx] + sig_fast(zi) * tanh_fast(zg);
            g_c[idx] = cn;
            float hn = sig_fast(zo) * tanh_fast(cn);

            __nv_bfloat16 hhi = __float2bfloat16_rn(hn);
            __nv_bfloat16 hlo = __float2bfloat16_rn(hn - __bfloat162float(hhi));
            hn_hi[idx] = hhi;
            hn_lo[idx] = hlo;
            if (t == Tt - 1) out[idx] = hn;
        }

        if (t == Tt - 1) break;   // no barrier needed after last step

        // ---- per-batch-group barrier (16 CTAs sharing this b0) ----
        __syncthreads();
        if (tid == 0) {
            __threadfence();
            atomicAdd(bar, 1u);
            unsigned int target = (unsigned int)(t + 1) * nPeers;
            while (*(volatile unsigned int*)bar < target) { }
        }
        __syncthreads();

        // ---- load next h (written by this batch group, fenced above) ----
        load_A(g_h_hi[(t + 1) & 1], g_h_lo[(t + 1) & 1]);
        cp_commit();
        cp_wait<0>();
        __syncthreads();
    }
}

// ---------------------------------------------------------------------------
// Launch (stateless, capture-safe)
// ---------------------------------------------------------------------------
extern "C" void kernel_launch(void* const* d_in, const int* in_sizes, int n_in,
                              void* d_out, int out_size)
{
    const float* x    = (const float*)d_in[0];   // [256, 128, 1280]
    const float* W    = (const float*)d_in[1];   // [1280, 1024]
    const float* R    = (const float*)d_in[2];   // [256, 1024]
    const float* bias = (const float*)d_in[3];   // [1024]
    float* out = (float*)d_out;                  // [256, 256]

    (void)in_sizes; (void)n_in; (void)out_size;

    init_state_kernel<<<(Bm * Hh + 511) / 512, 512>>>();

    // One-shot conversions
    convert_w_kernel<<<dim3(G4 / 32, Ff / 32), dim3(32, 8)>>>(W);
    convert_r_kernel<<<dim3(G4 / 32, Hh / 32), dim3(32, 8)>>>(R);
    convert_x_kernel<<<(unsigned)(((size_t)Bm * Tt * Ff / 4 + 255) / 256), 256>>>(x);

    // Phase 1: xz = x @ W + bias (mma.sync tensor cores, 3-stage cp.async)
    gemm_xz_kernel<<<dim3(G4 / 128, (Bm * Tt) / 128), 256>>>(bias);

    // Phase 2: one persistent kernel, 128 timesteps, per-group barriers,
    // 512 threads for MMA latency hiding.
    cudaFuncSetAttribute(lstm_persistent_kernel,
                         cudaFuncAttributeMaxDynamicSharedMemorySize, P2_SMEM);
    lstm_persistent_kernel<<<dim3(Hh / 16, Bm / 32), P2_THREADS, P2_SMEM>>>(out);
}